// round 4
// baseline (speedup 1.0000x reference)
#include <cuda_runtime.h>

// Problem constants
#define S_GRID 14
#define NCLS   20
#define N_IMG  4096
#define CELLS  (N_IMG * S_GRID * S_GRID)   // 802816
#define PRED_C 30
#define TPB    128
#define NBLK   (CELLS / TPB)               // 6272 (exact)

// Persistent device state. Zero-initialized at module load; the finalizing
// block resets it at the end of every launch, so each graph replay starts clean.
__device__ double g_acc[4];    // [0]=cls, [1]=noobj, [2]=containing, [3]=reg
__device__ unsigned int g_done;

__global__ void __launch_bounds__(TPB) yolo_fused_kernel(
    const float* __restrict__ pred,   // [CELLS, 30]
    const float* __restrict__ tbox,   // [CELLS, 4]
    const float* __restrict__ tcls,   // [CELLS, 20]
    const int*   __restrict__ mask,   // [CELLS]
    float*       __restrict__ out)    // [5]
{
    __shared__ float sp[TPB * PRED_C];  // 15360 B
    __shared__ float sc[TPB * NCLS];    // 10240 B

    const int t    = threadIdx.x;
    const int base = blockIdx.x * TPB;

    // ---- stage pred tile: TPB*30 floats = TPB*15 float2, fully coalesced ----
    {
        const float2* g = reinterpret_cast<const float2*>(pred + (size_t)base * PRED_C);
        float2*       s = reinterpret_cast<float2*>(sp);
        #pragma unroll
        for (int j = 0; j < PRED_C / 2; j++)
            s[j * TPB + t] = g[j * TPB + t];
    }
    // ---- stage tcls tile: TPB*20 floats = TPB*5 float4, fully coalesced ----
    {
        const float4* g = reinterpret_cast<const float4*>(tcls + (size_t)base * NCLS);
        float4*       s = reinterpret_cast<float4*>(sc);
        #pragma unroll
        for (int j = 0; j < NCLS / 4; j++)
            s[j * TPB + t] = g[j * TPB + t];
    }

    // ---- per-cell scalars (already coalesced in global) ----
    const float4 tb = reinterpret_cast<const float4*>(tbox)[base + t];
    const float  m  = (mask[base + t] != 0) ? 1.0f : 0.0f;

    __syncthreads();

    const float* pr = sp + t * PRED_C;  // word-stride 30: LDS.64 conflict-free
    const float* tc = sc + t * NCLS;    // word-stride 20: LDS.128 conflict-free

    // ---- class loss: m * sum (pred_cls - target_cls)^2 ----
    float s = 0.f;
    #pragma unroll
    for (int j = 0; j < NCLS / 4; j++) {
        const float4 c = reinterpret_cast<const float4*>(tc)[j];
        const float q0 = pr[10 + 4 * j + 0] - c.x;
        const float q1 = pr[10 + 4 * j + 1] - c.y;
        const float q2 = pr[10 + 4 * j + 2] - c.z;
        const float q3 = pr[10 + 4 * j + 3] - c.w;
        s += q0 * q0 + q1 * q1 + q2 * q2 + q3 * q3;
    }
    float cls_s = m * s;

    // ---- no-object loss: (1-m) * sum_b conf_b^2 ----
    const float c0 = pr[4], c1 = pr[9];
    float noobj_s = (1.0f - m) * (c0 * c0 + c1 * c1);

    // ---- IoU per box (B=2) ----
    float iou[2];
    #pragma unroll
    for (int b = 0; b < 2; b++) {
        const float x = pr[5 * b + 0] * (1.0f / S_GRID);
        const float y = pr[5 * b + 1] * (1.0f / S_GRID);
        const float w = pr[5 * b + 2];
        const float h = pr[5 * b + 3];
        const float p1x = x - w * 0.5f, p1y = y - h * 0.5f;
        const float p2x = x + w * 0.5f, p2y = y + h * 0.5f;
        const float ltx = fmaxf(p1x, tb.x), lty = fmaxf(p1y, tb.y);
        const float rbx = fminf(p2x, tb.z), rby = fminf(p2y, tb.w);
        const float iw = fmaxf(rbx - ltx, 0.0f);
        const float ih = fmaxf(rby - lty, 0.0f);
        const float inter  = iw * ih;
        const float area_p = w * h;
        const float area_t = (tb.z - tb.x) * (tb.w - tb.y);
        iou[b] = inter / (area_p + area_t - inter);
    }

    // argmax over B=2 (first occurrence of max, like jnp.argmax)
    const bool pick1 = (iou[1] > iou[0]);
    const float bx = pick1 ? pr[5] : pr[0];
    const float by = pick1 ? pr[6] : pr[1];
    const float bw = pick1 ? pr[7] : pr[2];
    const float bh = pick1 ? pr[8] : pr[3];
    const float bc = pick1 ? pr[9] : pr[4];

    // ---- containing-object loss ----
    float cont_s = m * (bc - 1.0f) * (bc - 1.0f);

    // ---- regression loss (center + dim) ----
    const float dx = bx - tb.x;
    const float dy = by - tb.y;
    const float dw = sqrtf(bw) - sqrtf(tb.z);
    const float dh = sqrtf(bh) - sqrtf(tb.w);
    float reg_s = m * (dx * dx + dy * dy + dw * dw + dh * dh);

    // ---- reduction: warp shuffle, then across 4 warps ----
    #pragma unroll
    for (int off = 16; off > 0; off >>= 1) {
        cls_s   += __shfl_down_sync(0xFFFFFFFFu, cls_s,   off);
        noobj_s += __shfl_down_sync(0xFFFFFFFFu, noobj_s, off);
        cont_s  += __shfl_down_sync(0xFFFFFFFFu, cont_s,  off);
        reg_s   += __shfl_down_sync(0xFFFFFFFFu, reg_s,   off);
    }

    __shared__ float sh[4][4];  // 128 threads -> 4 warps
    const int wid = t >> 5;
    const int lid = t & 31;
    if (lid == 0) {
        sh[0][wid] = cls_s;
        sh[1][wid] = noobj_s;
        sh[2][wid] = cont_s;
        sh[3][wid] = reg_s;
    }
    __syncthreads();

    if (t == 0) {
        float v0 = sh[0][0] + sh[0][1] + sh[0][2] + sh[0][3];
        float v1 = sh[1][0] + sh[1][1] + sh[1][2] + sh[1][3];
        float v2 = sh[2][0] + sh[2][1] + sh[2][2] + sh[2][3];
        float v3 = sh[3][0] + sh[3][1] + sh[3][2] + sh[3][3];
        atomicAdd(&g_acc[0], (double)v0);
        atomicAdd(&g_acc[1], (double)v1);
        atomicAdd(&g_acc[2], (double)v2);
        atomicAdd(&g_acc[3], (double)v3);

        __threadfence();
        const unsigned int old = atomicAdd(&g_done, 1u);
        if (old == (unsigned int)(gridDim.x - 1)) {
            // Last block: finalize + reset for the next graph replay.
            // Read accumulators through the atomic path (same L2 route the
            // other blocks' atomicAdds used) to sidestep any L1 staleness.
            const double cls_t   = atomicAdd(&g_acc[0], 0.0);
            const double noobj_t = atomicAdd(&g_acc[1], 0.0);
            const double cont_t  = atomicAdd(&g_acc[2], 0.0);
            const double reg_t   = atomicAdd(&g_acc[3], 0.0);
            const double inv_n = 1.0 / (double)N_IMG;
            const double cls   = cls_t   * inv_n;
            const double noobj = noobj_t * inv_n;
            const double cont  = cont_t  * inv_n;
            const double reg   = reg_t   * inv_n;
            out[0] = (float)(cls + 0.5 * noobj + 5.0 * reg + cont);
            out[1] = (float)reg;
            out[2] = (float)cont;
            out[3] = (float)noobj;
            out[4] = (float)cls;
            g_acc[0] = 0.0; g_acc[1] = 0.0; g_acc[2] = 0.0; g_acc[3] = 0.0;
            __threadfence();
            g_done = 0u;
        }
    }
}

extern "C" void kernel_launch(void* const* d_in, const int* in_sizes, int n_in,
                              void* d_out, int out_size) {
    // Identify inputs by element count (robust to ordering):
    //   pred: 24,084,480   tbox: 3,211,264   tcls: 16,056,320   mask: 802,816
    const float* pred = nullptr;
    const float* tbox = nullptr;
    const float* tcls = nullptr;
    const int*   msk  = nullptr;
    for (int k = 0; k < n_in; k++) {
        const long long sz = in_sizes[k];
        if      (sz == (long long)CELLS * PRED_C) pred = (const float*)d_in[k];
        else if (sz == (long long)CELLS * 4)      tbox = (const float*)d_in[k];
        else if (sz == (long long)CELLS * NCLS)   tcls = (const float*)d_in[k];
        else if (sz == (long long)CELLS)          msk  = (const int*)d_in[k];
    }
    float* out = (float*)d_out;

    yolo_fused_kernel<<<NBLK, TPB>>>(pred, tbox, tcls, msk, out);
}

// round 6
// speedup vs baseline: 1.1323x; 1.1323x over previous
#include <cuda_runtime.h>

// Problem constants
#define S_GRID 14
#define NCLS   20
#define N_IMG  4096
#define CELLS  (N_IMG * S_GRID * S_GRID)   // 802816
#define PRED_C 30
#define TPB    256
#define NBLK   (CELLS / TPB)               // 3136 (exact)

// Persistent device state. Zero-initialized at module load; the finalizing
// block resets it at the end of every launch, so each graph replay starts clean.
__device__ double g_acc[4];    // [0]=cls, [1]=noobj, [2]=containing, [3]=reg
__device__ unsigned int g_done;

__global__ void __launch_bounds__(TPB) yolo_fused_kernel(
    const float* __restrict__ pred,   // [CELLS, 30]
    const float* __restrict__ tbox,   // [CELLS, 4]
    const float* __restrict__ tcls,   // [CELLS, 20]
    const int*   __restrict__ mask,   // [CELLS]
    float*       __restrict__ out)    // [5]
{
    const int i = blockIdx.x * TPB + threadIdx.x;

    // ================= front-batched independent loads (MLP ~21) =================
    float p[PRED_C];
    {
        const float2* p2 = reinterpret_cast<const float2*>(pred + (size_t)i * PRED_C);
        #pragma unroll
        for (int j = 0; j < PRED_C / 2; j++) {
            const float2 v = p2[j];
            p[2 * j]     = v.x;
            p[2 * j + 1] = v.y;
        }
    }
    const float4 tb = reinterpret_cast<const float4*>(tbox)[i];

    float4 tc[NCLS / 4];
    {
        const float4* tc4 = reinterpret_cast<const float4*>(tcls + (size_t)i * NCLS);
        #pragma unroll
        for (int j = 0; j < NCLS / 4; j++) tc[j] = tc4[j];
    }
    const float m = (mask[i] != 0) ? 1.0f : 0.0f;

    // ================= compute =================
    // ---- class loss: m * sum (pred_cls - target_cls)^2 ----
    float s = 0.f;
    #pragma unroll
    for (int j = 0; j < NCLS / 4; j++) {
        const float q0 = p[10 + 4 * j + 0] - tc[j].x;
        const float q1 = p[10 + 4 * j + 1] - tc[j].y;
        const float q2 = p[10 + 4 * j + 2] - tc[j].z;
        const float q3 = p[10 + 4 * j + 3] - tc[j].w;
        s += q0 * q0 + q1 * q1 + q2 * q2 + q3 * q3;
    }
    float cls_s = m * s;

    // ---- no-object loss: (1-m) * sum_b conf_b^2 ----
    const float c0 = p[4], c1 = p[9];
    float noobj_s = (1.0f - m) * (c0 * c0 + c1 * c1);

    // ---- IoU per box (B=2) ----
    float iou[2];
    #pragma unroll
    for (int b = 0; b < 2; b++) {
        const float x = p[5 * b + 0] * (1.0f / S_GRID);
        const float y = p[5 * b + 1] * (1.0f / S_GRID);
        const float w = p[5 * b + 2];
        const float h = p[5 * b + 3];
        const float p1x = x - w * 0.5f, p1y = y - h * 0.5f;
        const float p2x = x + w * 0.5f, p2y = y + h * 0.5f;
        const float ltx = fmaxf(p1x, tb.x), lty = fmaxf(p1y, tb.y);
        const float rbx = fminf(p2x, tb.z), rby = fminf(p2y, tb.w);
        const float iw = fmaxf(rbx - ltx, 0.0f);
        const float ih = fmaxf(rby - lty, 0.0f);
        const float inter  = iw * ih;
        const float area_p = w * h;
        const float area_t = (tb.z - tb.x) * (tb.w - tb.y);
        iou[b] = inter / (area_p + area_t - inter);
    }

    // argmax over B=2 (first occurrence of max, like jnp.argmax)
    const bool pick1 = (iou[1] > iou[0]);
    const float bx = pick1 ? p[5] : p[0];
    const float by = pick1 ? p[6] : p[1];
    const float bw = pick1 ? p[7] : p[2];
    const float bh = pick1 ? p[8] : p[3];
    const float bc = pick1 ? p[9] : p[4];

    // ---- containing-object loss ----
    float cont_s = m * (bc - 1.0f) * (bc - 1.0f);

    // ---- regression loss (center + dim) ----
    const float dx = bx - tb.x;
    const float dy = by - tb.y;
    const float dw = sqrtf(bw) - sqrtf(tb.z);
    const float dh = sqrtf(bh) - sqrtf(tb.w);
    float reg_s = m * (dx * dx + dy * dy + dw * dw + dh * dh);

    // ================= reduction: warp shuffle, then across 8 warps =================
    #pragma unroll
    for (int off = 16; off > 0; off >>= 1) {
        cls_s   += __shfl_down_sync(0xFFFFFFFFu, cls_s,   off);
        noobj_s += __shfl_down_sync(0xFFFFFFFFu, noobj_s, off);
        cont_s  += __shfl_down_sync(0xFFFFFFFFu, cont_s,  off);
        reg_s   += __shfl_down_sync(0xFFFFFFFFu, reg_s,   off);
    }

    __shared__ float sh[4][8];  // 256 threads -> 8 warps
    const int wid = threadIdx.x >> 5;
    const int lid = threadIdx.x & 31;
    if (lid == 0) {
        sh[0][wid] = cls_s;
        sh[1][wid] = noobj_s;
        sh[2][wid] = cont_s;
        sh[3][wid] = reg_s;
    }
    __syncthreads();

    if (wid == 0) {
        float v0 = (lid < 8) ? sh[0][lid] : 0.f;
        float v1 = (lid < 8) ? sh[1][lid] : 0.f;
        float v2 = (lid < 8) ? sh[2][lid] : 0.f;
        float v3 = (lid < 8) ? sh[3][lid] : 0.f;
        #pragma unroll
        for (int off = 4; off > 0; off >>= 1) {
            v0 += __shfl_down_sync(0xFFFFFFFFu, v0, off);
            v1 += __shfl_down_sync(0xFFFFFFFFu, v1, off);
            v2 += __shfl_down_sync(0xFFFFFFFFu, v2, off);
            v3 += __shfl_down_sync(0xFFFFFFFFu, v3, off);
        }
        if (lid == 0) {
            atomicAdd(&g_acc[0], (double)v0);
            atomicAdd(&g_acc[1], (double)v1);
            atomicAdd(&g_acc[2], (double)v2);
            atomicAdd(&g_acc[3], (double)v3);

            __threadfence();
            const unsigned int old = atomicAdd(&g_done, 1u);
            if (old == (unsigned int)(gridDim.x - 1)) {
                // Last block: finalize + reset for the next graph replay.
                // Read accumulators through the atomic path (same L2 route the
                // other blocks' atomicAdds used).
                const double cls_t   = atomicAdd(&g_acc[0], 0.0);
                const double noobj_t = atomicAdd(&g_acc[1], 0.0);
                const double cont_t  = atomicAdd(&g_acc[2], 0.0);
                const double reg_t   = atomicAdd(&g_acc[3], 0.0);
                const double inv_n = 1.0 / (double)N_IMG;
                const double cls   = cls_t   * inv_n;
                const double noobj = noobj_t * inv_n;
                const double cont  = cont_t  * inv_n;
                const double reg   = reg_t   * inv_n;
                out[0] = (float)(cls + 0.5 * noobj + 5.0 * reg + cont);
                out[1] = (float)reg;
                out[2] = (float)cont;
                out[3] = (float)noobj;
                out[4] = (float)cls;
                g_acc[0] = 0.0; g_acc[1] = 0.0; g_acc[2] = 0.0; g_acc[3] = 0.0;
                __threadfence();
                g_done = 0u;
            }
        }
    }
}

extern "C" void kernel_launch(void* const* d_in, const int* in_sizes, int n_in,
                              void* d_out, int out_size) {
    // Identify inputs by element count (robust to ordering):
    //   pred: 24,084,480   tbox: 3,211,264   tcls: 16,056,320   mask: 802,816
    const float* pred = nullptr;
    const float* tbox = nullptr;
    const float* tcls = nullptr;
    const int*   msk  = nullptr;
    for (int k = 0; k < n_in; k++) {
        const long long sz = in_sizes[k];
        if      (sz == (long long)CELLS * PRED_C) pred = (const float*)d_in[k];
        else if (sz == (long long)CELLS * 4)      tbox = (const float*)d_in[k];
        else if (sz == (long long)CELLS * NCLS)   tcls = (const float*)d_in[k];
        else if (sz == (long long)CELLS)          msk  = (const int*)d_in[k];
    }
    float* out = (float*)d_out;

    yolo_fused_kernel<<<NBLK, TPB>>>(pred, tbox, tcls, msk, out);
}

// round 7
// speedup vs baseline: 1.1390x; 1.0059x over previous
#include <cuda_runtime.h>

// Problem constants
#define S_GRID 14
#define NCLS   20
#define N_IMG  4096
#define CELLS  (N_IMG * S_GRID * S_GRID)   // 802816
#define PRED_C 30
#define TPB    256
#define NBLK   (CELLS / TPB)               // 3136 (exact)

// Persistent device state. Zero-initialized at module load; the finalizing
// block resets it at the end of every launch, so each graph replay starts clean.
__device__ double g_acc[4];    // [0]=cls, [1]=noobj, [2]=containing, [3]=reg
__device__ unsigned int g_done;

__global__ void __launch_bounds__(TPB) yolo_fused_kernel(
    const float* __restrict__ pred,   // [CELLS, 30]
    const float* __restrict__ tbox,   // [CELLS, 4]
    const float* __restrict__ tcls,   // [CELLS, 20]
    const int*   __restrict__ mask,   // [CELLS]
    float*       __restrict__ out)    // [5]
{
    // Stage ONLY pred through smem: it is the wavefront offender (15 strided
    // LDG.64 x 30 lines = 450 wf per warp-tile when loaded directly).
    // Coalesced LDG + conflict-free STS/LDS cost ~90 wf instead.
    __shared__ float sp[TPB * PRED_C];  // 30720 B

    const int t    = threadIdx.x;
    const int base = blockIdx.x * TPB;
    const int i    = base + t;

    // ---- stage pred tile: flat copy, fully coalesced (2 wf per LDG.64) ----
    {
        const float2* g = reinterpret_cast<const float2*>(pred + (size_t)base * PRED_C);
        float2*       s = reinterpret_cast<float2*>(sp);
        #pragma unroll
        for (int j = 0; j < PRED_C / 2; j++)
            s[j * TPB + t] = g[j * TPB + t];
    }

    // ---- direct per-cell loads (issued before the sync to overlap) ----
    const float4 tb = reinterpret_cast<const float4*>(tbox)[i];
    float4 tc[NCLS / 4];
    {
        const float4* tc4 = reinterpret_cast<const float4*>(tcls + (size_t)i * NCLS);
        #pragma unroll
        for (int j = 0; j < NCLS / 4; j++) tc[j] = tc4[j];
    }
    const float m = (mask[i] != 0) ? 1.0f : 0.0f;

    __syncthreads();

    // ---- pull this thread's pred row from smem (15 LDS.64, stride-30 words:
    //      bank = (-2t) mod 32 per 16-lane phase, all distinct -> conflict-free)
    float p[PRED_C];
    {
        const float2* pr2 = reinterpret_cast<const float2*>(sp + t * PRED_C);
        #pragma unroll
        for (int k = 0; k < PRED_C / 2; k++) {
            const float2 v = pr2[k];
            p[2 * k]     = v.x;
            p[2 * k + 1] = v.y;
        }
    }

    // ================= compute =================
    // ---- class loss: m * sum (pred_cls - target_cls)^2 ----
    float s = 0.f;
    #pragma unroll
    for (int j = 0; j < NCLS / 4; j++) {
        const float q0 = p[10 + 4 * j + 0] - tc[j].x;
        const float q1 = p[10 + 4 * j + 1] - tc[j].y;
        const float q2 = p[10 + 4 * j + 2] - tc[j].z;
        const float q3 = p[10 + 4 * j + 3] - tc[j].w;
        s += q0 * q0 + q1 * q1 + q2 * q2 + q3 * q3;
    }
    float cls_s = m * s;

    // ---- no-object loss: (1-m) * sum_b conf_b^2 ----
    const float c0 = p[4], c1 = p[9];
    float noobj_s = (1.0f - m) * (c0 * c0 + c1 * c1);

    // ---- IoU per box (B=2) ----
    float iou[2];
    #pragma unroll
    for (int b = 0; b < 2; b++) {
        const float x = p[5 * b + 0] * (1.0f / S_GRID);
        const float y = p[5 * b + 1] * (1.0f / S_GRID);
        const float w = p[5 * b + 2];
        const float h = p[5 * b + 3];
        const float p1x = x - w * 0.5f, p1y = y - h * 0.5f;
        const float p2x = x + w * 0.5f, p2y = y + h * 0.5f;
        const float ltx = fmaxf(p1x, tb.x), lty = fmaxf(p1y, tb.y);
        const float rbx = fminf(p2x, tb.z), rby = fminf(p2y, tb.w);
        const float iw = fmaxf(rbx - ltx, 0.0f);
        const float ih = fmaxf(rby - lty, 0.0f);
        const float inter  = iw * ih;
        const float area_p = w * h;
        const float area_t = (tb.z - tb.x) * (tb.w - tb.y);
        iou[b] = inter / (area_p + area_t - inter);
    }

    // argmax over B=2 (first occurrence of max, like jnp.argmax)
    const bool pick1 = (iou[1] > iou[0]);
    const float bx = pick1 ? p[5] : p[0];
    const float by = pick1 ? p[6] : p[1];
    const float bw = pick1 ? p[7] : p[2];
    const float bh = pick1 ? p[8] : p[3];
    const float bc = pick1 ? p[9] : p[4];

    // ---- containing-object loss ----
    float cont_s = m * (bc - 1.0f) * (bc - 1.0f);

    // ---- regression loss (center + dim) ----
    const float dx = bx - tb.x;
    const float dy = by - tb.y;
    const float dw = sqrtf(bw) - sqrtf(tb.z);
    const float dh = sqrtf(bh) - sqrtf(tb.w);
    float reg_s = m * (dx * dx + dy * dy + dw * dw + dh * dh);

    // ================= reduction: warp shuffle, then across 8 warps =================
    #pragma unroll
    for (int off = 16; off > 0; off >>= 1) {
        cls_s   += __shfl_down_sync(0xFFFFFFFFu, cls_s,   off);
        noobj_s += __shfl_down_sync(0xFFFFFFFFu, noobj_s, off);
        cont_s  += __shfl_down_sync(0xFFFFFFFFu, cont_s,  off);
        reg_s   += __shfl_down_sync(0xFFFFFFFFu, reg_s,   off);
    }

    __shared__ float sh[4][8];  // 256 threads -> 8 warps
    const int wid = t >> 5;
    const int lid = t & 31;
    if (lid == 0) {
        sh[0][wid] = cls_s;
        sh[1][wid] = noobj_s;
        sh[2][wid] = cont_s;
        sh[3][wid] = reg_s;
    }
    __syncthreads();

    if (wid == 0) {
        float v0 = (lid < 8) ? sh[0][lid] : 0.f;
        float v1 = (lid < 8) ? sh[1][lid] : 0.f;
        float v2 = (lid < 8) ? sh[2][lid] : 0.f;
        float v3 = (lid < 8) ? sh[3][lid] : 0.f;
        #pragma unroll
        for (int off = 4; off > 0; off >>= 1) {
            v0 += __shfl_down_sync(0xFFFFFFFFu, v0, off);
            v1 += __shfl_down_sync(0xFFFFFFFFu, v1, off);
            v2 += __shfl_down_sync(0xFFFFFFFFu, v2, off);
            v3 += __shfl_down_sync(0xFFFFFFFFu, v3, off);
        }
        if (lid == 0) {
            atomicAdd(&g_acc[0], (double)v0);
            atomicAdd(&g_acc[1], (double)v1);
            atomicAdd(&g_acc[2], (double)v2);
            atomicAdd(&g_acc[3], (double)v3);

            __threadfence();
            const unsigned int old = atomicAdd(&g_done, 1u);
            if (old == (unsigned int)(gridDim.x - 1)) {
                // Last block: finalize + reset for the next graph replay.
                const double cls_t   = atomicAdd(&g_acc[0], 0.0);
                const double noobj_t = atomicAdd(&g_acc[1], 0.0);
                const double cont_t  = atomicAdd(&g_acc[2], 0.0);
                const double reg_t   = atomicAdd(&g_acc[3], 0.0);
                const double inv_n = 1.0 / (double)N_IMG;
                const double cls   = cls_t   * inv_n;
                const double noobj = noobj_t * inv_n;
                const double cont  = cont_t  * inv_n;
                const double reg   = reg_t   * inv_n;
                out[0] = (float)(cls + 0.5 * noobj + 5.0 * reg + cont);
                out[1] = (float)reg;
                out[2] = (float)cont;
                out[3] = (float)noobj;
                out[4] = (float)cls;
                g_acc[0] = 0.0; g_acc[1] = 0.0; g_acc[2] = 0.0; g_acc[3] = 0.0;
                __threadfence();
                g_done = 0u;
            }
        }
    }
}

extern "C" void kernel_launch(void* const* d_in, const int* in_sizes, int n_in,
                              void* d_out, int out_size) {
    // Identify inputs by element count (robust to ordering):
    //   pred: 24,084,480   tbox: 3,211,264   tcls: 16,056,320   mask: 802,816
    const float* pred = nullptr;
    const float* tbox = nullptr;
    const float* tcls = nullptr;
    const int*   msk  = nullptr;
    for (int k = 0; k < n_in; k++) {
        const long long sz = in_sizes[k];
        if      (sz == (long long)CELLS * PRED_C) pred = (const float*)d_in[k];
        else if (sz == (long long)CELLS * 4)      tbox = (const float*)d_in[k];
        else if (sz == (long long)CELLS * NCLS)   tcls = (const float*)d_in[k];
        else if (sz == (long long)CELLS)          msk  = (const int*)d_in[k];
    }
    float* out = (float*)d_out;

    yolo_fused_kernel<<<NBLK, TPB>>>(pred, tbox, tcls, msk, out);
}